// round 2
// baseline (speedup 1.0000x reference)
#include <cuda_runtime.h>

#define BATCH 2
#define NPTS 4096
#define NQ    16384
#define AGG_K 451

// ---------------- scratch (device globals; no allocation allowed) ----------------
__device__ float g_feat[BATCH * NPTS * 448];   // point-major features [b][n][448]
__device__ int   g_gmax[BATCH * 256];          // float-bit max of f3 (post-relu >= 0)
__device__ float g_c1[BATCH * 256];            // folded global-feat bias for r1
__device__ float g_r1t[AGG_K * 256];           // transposed r1 (first 451 cols)
__device__ float g_r2t[256 * 128];
__device__ float g_r3t[128 * 64];

// ---------------- f32x2 packed helpers (sm_103a FFMA2 path) ----------------
__device__ __forceinline__ unsigned long long pk2(float x) {
    unsigned long long r;
    asm("mov.b64 %0, {%1, %1};" : "=l"(r) : "f"(x));
    return r;
}
__device__ __forceinline__ void fma2(unsigned long long& acc, unsigned long long a,
                                     unsigned long long b) {
    asm("fma.rn.f32x2 %0, %1, %2, %0;" : "+l"(acc) : "l"(a), "l"(b));
}
__device__ __forceinline__ void upk2(unsigned long long v, float& lo, float& hi) {
    asm("mov.b64 {%0, %1}, %2;" : "=f"(lo), "=f"(hi) : "l"(v));
}

// ---------------- prep: transpose regressor weights + zero gmax ----------------
__global__ void prep_kernel(const float* __restrict__ r1, const float* __restrict__ r2,
                            const float* __restrict__ r3) {
    int stride = gridDim.x * blockDim.x;
    int tid = blockIdx.x * blockDim.x + threadIdx.x;
    if (tid < BATCH * 256) g_gmax[tid] = 0;
    for (int idx = tid; idx < AGG_K * 256; idx += stride) {
        int oc = idx & 255, k = idx >> 8;
        g_r1t[idx] = r1[oc * 707 + k];
    }
    for (int idx = tid; idx < 256 * 128; idx += stride) {
        int oc = idx & 127, k = idx >> 7;
        g_r2t[idx] = r2[oc * 256 + k];
    }
    for (int idx = tid; idx < 128 * 64; idx += stride) {
        int oc = idx & 63, k = idx >> 6;
        g_r3t[idx] = r3[oc * 128 + k];
    }
}

// ---------------- feature extractor: fused 3-layer 1x1-conv MLP ----------------
// grid = BATCH * (NPTS/32) blocks, 256 threads. Writes point-major g_feat + gmax.
__global__ void feat_kernel(const float* __restrict__ opts,
                            const float* __restrict__ w1, const float* __restrict__ b1,
                            const float* __restrict__ w2, const float* __restrict__ b2,
                            const float* __restrict__ w3, const float* __restrict__ b3) {
    extern __shared__ float sm[];
    float* w2t = sm;             // 64 *129 = 8256
    float* w3t = w2t + 8256;     // 128*257 = 32896
    float* f1s = w3t + 32896;    // 64 *33  = 2112
    float* f2s = f1s + 2112;     // 128*33  = 4224
    float* pts = f2s + 4224;     // 96
    int t = threadIdx.x;
    int bb = blockIdx.x >> 7;
    int base = (blockIdx.x & 127) * 32;

    for (int i = t; i < 128 * 64; i += 256) { int oc = i >> 6, k = i & 63; w2t[k * 129 + oc] = w2[i]; }
    for (int i = t; i < 256 * 128; i += 256) { int oc = i >> 7, k = i & 127; w3t[k * 257 + oc] = w3[i]; }
    for (int i = t; i < 96; i += 256) {
        int d = i >> 5, j = i & 31;
        pts[i] = opts[bb * 3 * NPTS + d * NPTS + base + j];
    }
    __syncthreads();

    // stage 1: 3 -> 64
    {
        int oc = t & 63, jg = t >> 6;
        float wx = w1[oc * 3], wy = w1[oc * 3 + 1], wz = w1[oc * 3 + 2], bia = b1[oc];
        #pragma unroll
        for (int j = jg * 8; j < jg * 8 + 8; j++) {
            float v = fmaf(wx, pts[j], fmaf(wy, pts[32 + j], fmaf(wz, pts[64 + j], bia)));
            v = fmaxf(v, 0.f);
            f1s[oc * 33 + j] = v;
            g_feat[(bb * NPTS + base + j) * 448 + oc] = v;
        }
    }
    __syncthreads();

    // stage 2: 64 -> 128
    {
        int oc = t & 127, half = t >> 7;
        float acc[16];
        float bia = b2[oc];
        #pragma unroll
        for (int i = 0; i < 16; i++) acc[i] = bia;
        for (int k = 0; k < 64; k++) {
            float w = w2t[k * 129 + oc];
            const float* f = &f1s[k * 33 + half * 16];
            #pragma unroll
            for (int i = 0; i < 16; i++) acc[i] = fmaf(w, f[i], acc[i]);
        }
        for (int i = 0; i < 16; i++) {
            float v = fmaxf(acc[i], 0.f);
            int j = half * 16 + i;
            f2s[oc * 33 + j] = v;
            g_feat[(bb * NPTS + base + j) * 448 + 64 + oc] = v;
        }
    }
    __syncthreads();

    // stage 3: 128 -> 256, plus running max for global feature
    {
        int oc = t;
        float acc[32];
        float bia = b3[oc];
        #pragma unroll
        for (int i = 0; i < 32; i++) acc[i] = bia;
        for (int k = 0; k < 128; k++) {
            float w = w3t[k * 257 + oc];
            const float* f = &f2s[k * 33];
            #pragma unroll
            for (int j = 0; j < 32; j++) acc[j] = fmaf(w, f[j], acc[j]);
        }
        float mx = 0.f;
        for (int j = 0; j < 32; j++) {
            float v = fmaxf(acc[j], 0.f);
            g_feat[(bb * NPTS + base + j) * 448 + 192 + oc] = v;
            mx = fmaxf(mx, v);
        }
        atomicMax(&g_gmax[bb * 256 + oc], __float_as_int(mx));  // valid: mx >= 0
    }
}

// ---------------- fold global feats into r1 bias ----------------
// grid = BATCH*8, block 256; block handles 32 ocs, 8 threads per oc.
__global__ void c1_kernel(const float* __restrict__ r1, const float* __restrict__ rb1) {
    __shared__ float fms[256];
    int t = threadIdx.x;
    int bb = blockIdx.x >> 3;
    int ocbase = (blockIdx.x & 7) * 32;
    fms[t] = __int_as_float(g_gmax[bb * 256 + t]);
    __syncthreads();
    int oc = ocbase + (t >> 3);
    int seg = t & 7;
    const float* row = r1 + oc * 707 + 451 + seg * 32;
    float s = 0.f;
    #pragma unroll
    for (int i = 0; i < 32; i++) s = fmaf(row[i], fms[seg * 32 + i], s);
    s += __shfl_xor_sync(0xffffffffu, s, 1);
    s += __shfl_xor_sync(0xffffffffu, s, 2);
    s += __shfl_xor_sync(0xffffffffu, s, 4);
    if (seg == 0) g_c1[bb * 256 + oc] = s + rb1[oc];
}

// ---------------- warp top-3 merge (select-chain, no local arrays) ----------------
__device__ __forceinline__ void merge3(float b0, float b1, float b2,
                                       int i0, int i1, int i2, int lane, int sel[3]) {
    int j = 0;
    #pragma unroll
    for (int s = 0; s < 3; s++) {
        float cv = (j == 0) ? b0 : ((j == 1) ? b1 : ((j == 2) ? b2 : 3.4e38f));
        int   ci = (j == 0) ? i0 : ((j == 1) ? i1 : i2);
        float rv = cv; int rl = lane;
        #pragma unroll
        for (int off = 16; off; off >>= 1) {
            float ov = __shfl_down_sync(0xffffffffu, rv, off);
            int   ol = __shfl_down_sync(0xffffffffu, rl, off);
            if (ov < rv) { rv = ov; rl = ol; }
        }
        int wl = __shfl_sync(0xffffffffu, rl, 0);
        sel[s] = __shfl_sync(0xffffffffu, ci, wl);
        if (lane == wl) j++;
    }
}

// ---------------- fused KNN(3) + interpolation + regressor ----------------
// grid = BATCH * (NQ/32) blocks, 256 threads; 32 queries/block, 4 queries/warp.
__global__ void __launch_bounds__(256) knnreg_kernel(
        const float* __restrict__ opts, const float* __restrict__ qpts,
        const float* __restrict__ rb2, const float* __restrict__ rb3,
        const float* __restrict__ r4, const float* __restrict__ rb4,
        float* __restrict__ out) {
    extern __shared__ float sm[];
    float* aggs = sm;            // 451*34 = 15334 floats
    float* spt  = sm + 15334;    // 3*4096 = 12288 floats (dead after KNN)
    float* h1s  = sm + 15334;    // 256*34 = 8704  (overlays spt)
    float* h2s  = sm;            // 128*34 = 4352  (overlays aggs)
    float* h3s  = sm + 4352;     // 64*34  = 2176
    int t = threadIdx.x;
    int bb = blockIdx.x >> 9, tile = blockIdx.x & 511;
    int qbase = tile * 32;

    for (int i = t; i < NPTS; i += 256) {
        spt[i]            = opts[bb * 3 * NPTS + i];
        spt[NPTS + i]     = opts[bb * 3 * NPTS + NPTS + i];
        spt[2 * NPTS + i] = opts[bb * 3 * NPTS + 2 * NPTS + i];
    }
    __syncthreads();
    const float* sx = spt;
    const float* sy = spt + NPTS;
    const float* sz = spt + 2 * NPTS;

    int warp = t >> 5, lane = t & 31;
    int q0 = qbase + warp * 4;
    float qx[4], qy[4], qz[4];
    #pragma unroll
    for (int r = 0; r < 4; r++) {
        qx[r] = qpts[bb * 3 * NQ + q0 + r];
        qy[r] = qpts[bb * 3 * NQ + NQ + q0 + r];
        qz[r] = qpts[bb * 3 * NQ + 2 * NQ + q0 + r];
    }

    float bd[4][3];
    int   bi[4][3];
    #pragma unroll
    for (int r = 0; r < 4; r++)
        #pragma unroll
        for (int s = 0; s < 3; s++) { bd[r][s] = 3.4e38f; bi[r][s] = 0; }

    for (int p = lane; p < NPTS; p += 32) {
        float x = sx[p], y = sy[p], z = sz[p];
        #pragma unroll
        for (int r = 0; r < 4; r++) {
            float dx = qx[r] - x, dy = qy[r] - y, dz = qz[r] - z;
            float dd = fmaf(dx, dx, fmaf(dy, dy, dz * dz));
            if (dd < bd[r][2]) {
                if (dd < bd[r][1]) {
                    bd[r][2] = bd[r][1]; bi[r][2] = bi[r][1];
                    if (dd < bd[r][0]) { bd[r][1] = bd[r][0]; bi[r][1] = bi[r][0]; bd[r][0] = dd; bi[r][0] = p; }
                    else               { bd[r][1] = dd; bi[r][1] = p; }
                } else { bd[r][2] = dd; bi[r][2] = p; }
            }
        }
    }

    #pragma unroll
    for (int r = 0; r < 4; r++) {
        int sel[3];
        merge3(bd[r][0], bd[r][1], bd[r][2], bi[r][0], bi[r][1], bi[r][2], lane, sel);
        int ql = warp * 4 + r;

        float wk[3], wsum = 0.f;
        #pragma unroll
        for (int s = 0; s < 3; s++) {
            int p = sel[s];
            float dx = qx[r] - sx[p], dy = qy[r] - sy[p], dz = qz[r] - sz[p];
            float dist = sqrtf(dx * dx + dy * dy + dz * dz);
            wk[s] = 1.f / (dist + 1e-8f);
            wsum += wk[s];
        }
        float inv = 1.f / wsum;
        wk[0] *= inv; wk[1] *= inv; wk[2] *= inv;

        if (lane == 0) {
            aggs[0 * 34 + ql] = qx[r];
            aggs[1 * 34 + ql] = qy[r];
            aggs[2 * 34 + ql] = qz[r];
        }
        const float* F0 = g_feat + (size_t)(bb * NPTS + sel[0]) * 448;
        const float* F1 = g_feat + (size_t)(bb * NPTS + sel[1]) * 448;
        const float* F2 = g_feat + (size_t)(bb * NPTS + sel[2]) * 448;
        for (int c = lane; c < 448; c += 32)
            aggs[(3 + c) * 34 + ql] = wk[0] * F0[c] + wk[1] * F1[c] + wk[2] * F2[c];
    }
    __syncthreads();

    // stage 1: 451 -> 256 (bias includes folded global-feat term)
    {
        int oc = t;
        unsigned long long acc[16];
        unsigned long long cinit = pk2(g_c1[bb * 256 + oc]);
        #pragma unroll
        for (int i = 0; i < 16; i++) acc[i] = cinit;
        #pragma unroll 2
        for (int k = 0; k < AGG_K; k++) {
            unsigned long long w = pk2(g_r1t[k * 256 + oc]);
            const unsigned long long* ap = (const unsigned long long*)(aggs + k * 34);
            #pragma unroll
            for (int i = 0; i < 16; i++) fma2(acc[i], w, ap[i]);
        }
        __syncthreads();  // aggs fully read before h1s overlays spt (different region, but keep order sane)
        #pragma unroll
        for (int i = 0; i < 16; i++) {
            float lo, hi;
            upk2(acc[i], lo, hi);
            h1s[oc * 34 + 2 * i]     = fmaxf(lo, 0.f);
            h1s[oc * 34 + 2 * i + 1] = fmaxf(hi, 0.f);
        }
    }
    __syncthreads();

    // stage 2: 256 -> 128 (writes over dead aggs region)
    {
        int oc = t & 127, half = t >> 7;
        unsigned long long acc[8];
        unsigned long long binit = pk2(rb2[oc]);
        #pragma unroll
        for (int i = 0; i < 8; i++) acc[i] = binit;
        #pragma unroll 2
        for (int k = 0; k < 256; k++) {
            unsigned long long w = pk2(g_r2t[k * 128 + oc]);
            const unsigned long long* ap = (const unsigned long long*)(h1s + k * 34) + half * 8;
            #pragma unroll
            for (int i = 0; i < 8; i++) fma2(acc[i], w, ap[i]);
        }
        #pragma unroll
        for (int i = 0; i < 8; i++) {
            float lo, hi;
            upk2(acc[i], lo, hi);
            int qp = half * 8 + i;
            h2s[oc * 34 + 2 * qp]     = fmaxf(lo, 0.f);
            h2s[oc * 34 + 2 * qp + 1] = fmaxf(hi, 0.f);
        }
    }
    __syncthreads();

    // stage 3: 128 -> 64
    {
        int oc = t & 63, qr = t >> 6;
        unsigned long long acc[4];
        unsigned long long binit = pk2(rb3[oc]);
        #pragma unroll
        for (int i = 0; i < 4; i++) acc[i] = binit;
        #pragma unroll 2
        for (int k = 0; k < 128; k++) {
            unsigned long long w = pk2(g_r3t[k * 64 + oc]);
            const unsigned long long* ap = (const unsigned long long*)(h2s + k * 34) + qr * 4;
            #pragma unroll
            for (int i = 0; i < 4; i++) fma2(acc[i], w, ap[i]);
        }
        #pragma unroll
        for (int i = 0; i < 4; i++) {
            float lo, hi;
            upk2(acc[i], lo, hi);
            int qp = qr * 4 + i;
            h3s[oc * 34 + 2 * qp]     = fmaxf(lo, 0.f);
            h3s[oc * 34 + 2 * qp + 1] = fmaxf(hi, 0.f);
        }
    }
    __syncthreads();

    // stage 4: 64 -> 1
    {
        int w4 = t >> 5, l4 = t & 31;
        int qloc = w4 * 4 + (l4 >> 3);
        int c0 = l4 & 7;
        float p = 0.f;
        #pragma unroll
        for (int jj = 0; jj < 8; jj++) {
            int c = c0 + jj * 8;
            p = fmaf(r4[c], h3s[c * 34 + qloc], p);
        }
        p += __shfl_xor_sync(0xffffffffu, p, 1);
        p += __shfl_xor_sync(0xffffffffu, p, 2);
        p += __shfl_xor_sync(0xffffffffu, p, 4);
        if ((l4 & 7) == 0) out[bb * NQ + qbase + qloc] = p + rb4[0];
    }
}

// ---------------- launch ----------------
extern "C" void kernel_launch(void* const* d_in, const int* in_sizes, int n_in,
                              void* d_out, int out_size) {
    const float* opts = (const float*)d_in[0];
    const float* qpts = (const float*)d_in[1];
    const float* w1 = (const float*)d_in[2];
    const float* b1 = (const float*)d_in[3];
    const float* w2 = (const float*)d_in[4];
    const float* b2 = (const float*)d_in[5];
    const float* w3 = (const float*)d_in[6];
    const float* b3 = (const float*)d_in[7];
    const float* r1 = (const float*)d_in[8];
    const float* rb1 = (const float*)d_in[9];
    const float* r2 = (const float*)d_in[10];
    const float* rb2 = (const float*)d_in[11];
    const float* r3 = (const float*)d_in[12];
    const float* rb3 = (const float*)d_in[13];
    const float* r4 = (const float*)d_in[14];
    const float* rb4 = (const float*)d_in[15];
    float* out = (float*)d_out;

    cudaFuncSetAttribute(feat_kernel, cudaFuncAttributeMaxDynamicSharedMemorySize, 190336);
    cudaFuncSetAttribute(knnreg_kernel, cudaFuncAttributeMaxDynamicSharedMemorySize, 110488);

    prep_kernel<<<64, 256>>>(r1, r2, r3);
    feat_kernel<<<BATCH * (NPTS / 32), 256, 190336>>>(opts, w1, b1, w2, b2, w3, b3);
    c1_kernel<<<BATCH * 8, 256>>>(r1, rb1);
    knnreg_kernel<<<BATCH * (NQ / 32), 256, 110488>>>(opts, qpts, rb2, rb3, r4, rb4, out);
}